// round 14
// baseline (speedup 1.0000x reference)
#include <cuda_runtime.h>
#include <math.h>
#include <stdint.h>

// ---------------- scratch (device globals, no allocation) ----------------
typedef unsigned long long ull;
__device__ float g_cwT[512 * 64];          // conv_w transposed [d][k]
__device__ float g_vpart[25 * 8 * 32768];  // [ntile][b][d*64+k] vlad partials
__device__ float g_vlad[8 * 32768];        // [b][d*64+k] centered + scaled desc
__device__ float g_asum[8 * 64];           // [b][k] total assign sums
__device__ float g_ksum[8 * 64];           // [b][k] sum of squares over d
__device__ unsigned g_cntb[8];             // per-batch block-completion counters
__device__ float g_wpart[2 * 8 * 4096];    // [ksplit][b][out] whiten partials

#define EPSN 1e-12f

__device__ __forceinline__ void ffma2(ull& acc, ull a, ull b) {
    asm("fma.rn.f32x2 %0, %1, %2, %0;" : "+l"(acc) : "l"(a), "l"(b));
}
__device__ __forceinline__ ull pack2(float v) {
    ull r; asm("mov.b64 %0, {%1, %1};" : "=l"(r) : "f"(v)); return r;
}
__device__ __forceinline__ ull packab(float a, float b) {
    ull r; asm("mov.b64 %0, {%1, %2};" : "=l"(r) : "f"(a), "f"(b)); return r;
}
__device__ __forceinline__ float2 unpack2(ull v) {
    float2 f; asm("mov.b64 {%0, %1}, %2;" : "=f"(f.x), "=f"(f.y) : "l"(v)); return f;
}
__device__ __forceinline__ void cpa16(uint32_t s, const void* g) {
    asm volatile("cp.async.cg.shared.global [%0], [%1], 16;" :: "r"(s), "l"(g));
}
__device__ __forceinline__ void cpa_commit() { asm volatile("cp.async.commit_group;"); }
__device__ __forceinline__ void pref_l2(const void* p) {
    asm volatile("prefetch.global.L2 [%0];" :: "l"(p));
}

// ---------------- prep: transpose conv_w + zero accumulators + reset counters ----------------
__global__ void k_prep(const float* __restrict__ cw) {
    const int k = blockIdx.x;
    const int d = threadIdx.x;
    g_cwT[d * 64 + k] = cw[k * 512 + d];
    if (blockIdx.x == 0) {
        g_asum[d & 511] = 0.0f;
        g_ksum[d & 511] = 0.0f;
        if (d < 8) g_cntb[d] = 0u;
    }
}

// ---------------- fused scores + softmax + vlad-gemm (+ L2 warm of W) ----------------
// grid (25, 8): n-tile of 64, batch. block 256 = 16x16. 85KB dyn smem, occ 2.
__global__ __launch_bounds__(256, 2) void k_fused(const float* __restrict__ x,
                                                  const float* __restrict__ W) {
    extern __shared__ __align__(16) float smf[];
    float* XB0 = smf;
    float* XB1 = smf + 4352;
    float* CB0 = smf + 8704;
    float* CB1 = smf + 13056;
    float* SC  = smf + 17408;          // scores [k][n] then assignT n-pairs (ull [n2][k])
    float* inv_sum = smf + 21760;      // 64 floats

    const int b = blockIdx.y;
    const int n0 = blockIdx.x * 64;
    const int t = threadIdx.x;
    const int tx = t & 15;
    const int ty = t >> 4;
    const int cta = blockIdx.y * 25 + blockIdx.x;   // 0..199

    const float* xb = x + (size_t)b * 512 * 1600;

    // W L2-warm: 16 iterations x 256 threads = 4096 lines/CTA (512KB), 200 CTAs = 102MB
    auto warm = [&](int iter) {
        const int L = (cta * 16 + iter) * 256 + t;   // < 819200
        const int row = L / 200;                      // < 4096
        const int rem = L % 200;
        const int half = rem / 100;
        const int li = rem % 100;
        pref_l2(W + (size_t)row * 32768 + half * 16384 + li * 32);
    };

    const uint32_t sx0 = (uint32_t)__cvta_generic_to_shared(XB0);
    const uint32_t sx1 = (uint32_t)__cvta_generic_to_shared(XB1);
    const uint32_t sc0 = (uint32_t)__cvta_generic_to_shared(CB0);
    const uint32_t sc1 = (uint32_t)__cvta_generic_to_shared(CB1);
    const int qdd = t >> 4;
    const int qn4 = t & 15;

    auto stage1 = [&](int tile, int buf) {
        const int d0 = tile * 64;
        const uint32_t bx = buf ? sx1 : sx0;
        const uint32_t bc = buf ? sc1 : sc0;
#pragma unroll
        for (int i = 0; i < 4; i++) {
            const int dd = qdd + i * 16;
            cpa16(bx + (uint32_t)((dd * 68 + qn4 * 4) * 4),
                  xb + (size_t)(d0 + dd) * 1600 + n0 + qn4 * 4);
            cpa16(bc + (uint32_t)((dd * 68 + qn4 * 4) * 4),
                  g_cwT + (d0 + dd) * 64 + qn4 * 4);
        }
        cpa_commit();
    };

    ull acc[4][2];
#pragma unroll
    for (int i = 0; i < 4; i++) { acc[i][0] = 0ULL; acc[i][1] = 0ULL; }

    stage1(0, 0);
    for (int tile = 0; tile < 8; tile++) {
        const int buf = tile & 1;
        if (tile < 7) {
            stage1(tile + 1, buf ^ 1);
            asm volatile("cp.async.wait_group 1;");
        } else {
            asm volatile("cp.async.wait_group 0;");
        }
        __syncthreads();
        warm(tile);

        const float* CS = buf ? CB1 : CB0;
        const float* XS = buf ? XB1 : XB0;
#pragma unroll 8
        for (int dd = 0; dd < 64; dd++) {
            float4 a = *(const float4*)&CS[dd * 68 + ty * 4];
            ulonglong2 f2 = *(const ulonglong2*)&XS[dd * 68 + tx * 4];
            ull a0 = pack2(a.x), a1 = pack2(a.y), a2 = pack2(a.z), a3 = pack2(a.w);
            ffma2(acc[0][0], a0, f2.x); ffma2(acc[0][1], a0, f2.y);
            ffma2(acc[1][0], a1, f2.x); ffma2(acc[1][1], a1, f2.y);
            ffma2(acc[2][0], a2, f2.x); ffma2(acc[2][1], a2, f2.y);
            ffma2(acc[3][0], a3, f2.x); ffma2(acc[3][1], a3, f2.y);
        }
        __syncthreads();
    }

#pragma unroll
    for (int i = 0; i < 4; i++)
#pragma unroll
        for (int p = 0; p < 2; p++) {
            float2 u = unpack2(acc[i][p]);
            SC[(ty * 4 + i) * 68 + tx * 4 + 2 * p]     = u.x;
            SC[(ty * 4 + i) * 68 + tx * 4 + 2 * p + 1] = u.y;
        }
    __syncthreads();

    if (t < 64) {
        const int n = t;
        float mx = -1e30f;
#pragma unroll 8
        for (int k = 0; k < 64; k++) mx = fmaxf(mx, SC[k * 68 + n]);
        float s = 0.0f;
#pragma unroll 8
        for (int k = 0; k < 64; k++) {
            float e = __expf(SC[k * 68 + n] - mx);
            SC[k * 68 + n] = e;
            s += e;
        }
        inv_sum[n] = 1.0f / s;
    }
    __syncthreads();
    if (t < 64) {
        const int k = t;
        float s = 0.0f;
#pragma unroll 8
        for (int nn = 0; nn < 64; nn++) {
            float a = SC[k * 68 + nn] * inv_sum[nn];
            SC[k * 68 + nn] = a;
            s += a;
        }
        atomicAdd(&g_asum[b * 64 + k], s);
    }
    __syncthreads();

    // repack SC [k][n] -> n-pair table ST2 (ull [n2][k], stride 68) in place
    ull* ST2 = (ull*)SC;
    {
        ull tmp[8];
#pragma unroll
        for (int i = 0; i < 8; i++) {
            const int idx = t + i * 256;       // 2048 slots: n2 = idx>>6, k = idx&63
            const int n2 = idx >> 6, k = idx & 63;
            tmp[i] = packab(SC[k * 68 + 2 * n2], SC[k * 68 + 2 * n2 + 1]);
        }
        __syncthreads();
#pragma unroll
        for (int i = 0; i < 8; i++) {
            const int idx = t + i * 256;
            const int n2 = idx >> 6, k = idx & 63;
            ST2[n2 * 68 + k] = tmp[i];
        }
    }

    auto stage2 = [&](int tile, int buf) {
        const int d0 = tile * 64;
        const uint32_t bx = buf ? sx1 : sx0;
#pragma unroll
        for (int i = 0; i < 4; i++) {
            const int dd = qdd + i * 16;
            cpa16(bx + (uint32_t)((dd * 68 + qn4 * 4) * 4),
                  xb + (size_t)(d0 + dd) * 1600 + n0 + qn4 * 4);
        }
        cpa_commit();
    };

    float* vp = g_vpart + ((size_t)blockIdx.x * 8 + b) * 32768;
    __syncthreads();
    stage2(0, 0);
    for (int tile = 0; tile < 8; tile++) {
        const int buf = tile & 1;
        if (tile < 7) {
            stage2(tile + 1, buf ^ 1);
            asm volatile("cp.async.wait_group 1;");
        } else {
            asm volatile("cp.async.wait_group 0;");
        }
        __syncthreads();
        warm(8 + tile);

        const float* XS2 = buf ? XB1 : XB0;
        // acc2[d][k]: lo half accumulates even n, hi half odd n
        ull acc2[4][4];
#pragma unroll
        for (int i = 0; i < 4; i++)
#pragma unroll
            for (int j = 0; j < 4; j++) acc2[i][j] = 0ULL;

#pragma unroll 4
        for (int n2 = 0; n2 < 32; n2++) {
            ulonglong2 ap0 = *(const ulonglong2*)&ST2[n2 * 68 + tx * 4];
            ulonglong2 ap1 = *(const ulonglong2*)&ST2[n2 * 68 + tx * 4 + 2];
            ull x0 = *(const ull*)&XS2[(ty * 4 + 0) * 68 + n2 * 2];
            ull x1 = *(const ull*)&XS2[(ty * 4 + 1) * 68 + n2 * 2];
            ull x2 = *(const ull*)&XS2[(ty * 4 + 2) * 68 + n2 * 2];
            ull x3 = *(const ull*)&XS2[(ty * 4 + 3) * 68 + n2 * 2];
            ffma2(acc2[0][0], x0, ap0.x); ffma2(acc2[0][1], x0, ap0.y);
            ffma2(acc2[0][2], x0, ap1.x); ffma2(acc2[0][3], x0, ap1.y);
            ffma2(acc2[1][0], x1, ap0.x); ffma2(acc2[1][1], x1, ap0.y);
            ffma2(acc2[1][2], x1, ap1.x); ffma2(acc2[1][3], x1, ap1.y);
            ffma2(acc2[2][0], x2, ap0.x); ffma2(acc2[2][1], x2, ap0.y);
            ffma2(acc2[2][2], x2, ap1.x); ffma2(acc2[2][3], x2, ap1.y);
            ffma2(acc2[3][0], x3, ap0.x); ffma2(acc2[3][1], x3, ap0.y);
            ffma2(acc2[3][2], x3, ap1.x); ffma2(acc2[3][3], x3, ap1.y);
        }
        const int d0 = tile * 64;
#pragma unroll
        for (int i = 0; i < 4; i++) {
            const int d = d0 + ty * 4 + i;
            float2 u0 = unpack2(acc2[i][0]);
            float2 u1 = unpack2(acc2[i][1]);
            float2 u2 = unpack2(acc2[i][2]);
            float2 u3 = unpack2(acc2[i][3]);
            float4 o;
            o.x = u0.x + u0.y; o.y = u1.x + u1.y;
            o.z = u2.x + u2.y; o.w = u3.x + u3.y;
            *(float4*)&vp[d * 64 + tx * 4] = o;
        }
        __syncthreads();
    }
}

// ---------------- post: sum 25 partials + centers fold + norms + scale ----------------
// grid (16, 8) = 128 CTAs, single wave. block 256; two float4 per thread.
__global__ __launch_bounds__(256) void k_post(const float* __restrict__ centers) {
    const int b = blockIdx.y;
    const int t = threadIdx.x;
    const int q = t & 15;

    const float4* c4p = (const float4*)centers;
    const float4* A4p = (const float4*)(g_asum + b * 64);
    const float4 A4 = A4p[q];

    float4 v[2];
    float4 ssq = make_float4(0.f, 0.f, 0.f, 0.f);
#pragma unroll
    for (int h = 0; h < 2; h++) {
        const int i4 = blockIdx.x * 512 + h * 256 + t;
        float4 acc = make_float4(0.f, 0.f, 0.f, 0.f);
#pragma unroll
        for (int s = 0; s < 25; s++) {
            float4 p = *(const float4*)(g_vpart + ((size_t)s * 8 + b) * 32768 + (size_t)i4 * 4);
            acc.x += p.x; acc.y += p.y; acc.z += p.z; acc.w += p.w;
        }
        const float4 c = c4p[i4];
        acc.x -= A4.x * c.x; acc.y -= A4.y * c.y; acc.z -= A4.z * c.z; acc.w -= A4.w * c.w;
        v[h] = acc;
        ssq.x += acc.x * acc.x; ssq.y += acc.y * acc.y;
        ssq.z += acc.z * acc.z; ssq.w += acc.w * acc.w;
    }

    __shared__ __align__(16) float4 red[256];
    red[t] = ssq;
    __syncthreads();
    if (t < 16) {
        float4 s = make_float4(0.f, 0.f, 0.f, 0.f);
#pragma unroll
        for (int j = 0; j < 16; j++) {
            float4 r = red[t + j * 16];
            s.x += r.x; s.y += r.y; s.z += r.z; s.w += r.w;
        }
        atomicAdd(&g_ksum[b * 64 + t * 4 + 0], s.x);
        atomicAdd(&g_ksum[b * 64 + t * 4 + 1], s.y);
        atomicAdd(&g_ksum[b * 64 + t * 4 + 2], s.z);
        atomicAdd(&g_ksum[b * 64 + t * 4 + 3], s.w);
    }
    __threadfence();
    __syncthreads();

    if (t == 0) {
        atomicAdd(&g_cntb[b], 1u);
        while (*(volatile unsigned*)&g_cntb[b] < 16u) { }
    }
    __syncthreads();
    __threadfence();

    __shared__ float sc_s[64];
    __shared__ float wred[2];
    float inv = 0.0f, contrib = 0.0f;
    if (t < 64) {
        float kv = *(volatile float*)&g_ksum[b * 64 + t];
        inv = 1.0f / fmaxf(sqrtf(kv), EPSN);
        contrib = kv * inv * inv;
    }
    float csum = contrib;
#pragma unroll
    for (int off = 16; off; off >>= 1) csum += __shfl_xor_sync(0xffffffffu, csum, off);
    if (t < 64 && (t & 31) == 0) wred[t >> 5] = csum;
    __syncthreads();
    if (t < 64) {
        float g = wred[0] + wred[1];
        sc_s[t] = inv * (1.0f / fmaxf(sqrtf(g), EPSN));
    }
    __syncthreads();

    const float4 sc4 = *(const float4*)&sc_s[q * 4];
    float4* vp = (float4*)(g_vlad + (size_t)b * 32768);
#pragma unroll
    for (int h = 0; h < 2; h++) {
        const int i4 = blockIdx.x * 512 + h * 256 + t;
        float4 o = v[h];
        o.x *= sc4.x; o.y *= sc4.y; o.z *= sc4.z; o.w *= sc4.w;
        vp[i4] = o;
    }
}

// ---------------- whitening GEMM v5: 64 rows/CTA, K-split 2, 5-stage ring ----------------
// grid 128 = 64 rowtiles x 2 K-halves = single wave, 1 CTA/SM. block 256 (8 warps x 8 rows).
// smem: W [5][8192]f at 0, D [5][1024]f at 40960 -> 180KB dyn.
__global__ __launch_bounds__(256, 1) void k_whiten(const float* __restrict__ W) {
    extern __shared__ __align__(16) float smw[];

    const int rowtile = blockIdx.x >> 1;
    const int ks = blockIdx.x & 1;
    const int o0 = rowtile * 64;
    const int jbase = ks * 16384;

    const int t = threadIdx.x;
    const int lane = t & 31;
    const int warp = t >> 5;
    const int r0 = warp * 8;
    const int c = lane * 4;
    const int wr = t >> 5;
    const int wc4 = t & 31;

    ull acc[8][8];
#pragma unroll
    for (int r = 0; r < 8; r++)
#pragma unroll
        for (int bb = 0; bb < 8; bb++) acc[r][bb] = 0ULL;

    const uint32_t sbase = (uint32_t)__cvta_generic_to_shared(smw);
    const float* Wbase = W + (size_t)o0 * 32768 + jbase;
    const float* Dbase = g_vlad + jbase;

    auto stage = [&](int tile, int buf) {
        const int jc = tile * 128 + wc4 * 4;
#pragma unroll
        for (int i = 0; i < 8; i++) {
            const int r = wr * 8 + i;
            cpa16(sbase + (uint32_t)((buf * 8192 + r * 128 + wc4 * 4) * 4),
                  Wbase + (size_t)r * 32768 + jc);
        }
        cpa16(sbase + (uint32_t)((40960 + buf * 1024 + wr * 128 + wc4 * 4) * 4),
              Dbase + (size_t)wr * 32768 + jc);
        cpa_commit();
    };

    stage(0, 0); stage(1, 1); stage(2, 2); stage(3, 3);

    int buf = 0, nbuf = 4;
    for (int tile = 0; tile < 128; tile++) {
        const int rem = 127 - tile;
        if (rem >= 3)      asm volatile("cp.async.wait_group 3;");
        else if (rem == 2) asm volatile("cp.async.wait_group 2;");
        else if (rem == 1) asm volatile("cp.async.wait_group 1;");
        else               asm volatile("cp.async.wait_group 0;");
        __syncthreads();
        if (tile + 4 < 128) {
            stage(tile + 4, nbuf);
            if (++nbuf == 5) nbuf = 0;
        }

        const float* Wt = smw + buf * 8192;
        const float* Dt = smw + 40960 + buf * 1024;
        if (++buf == 5) buf = 0;

        ulonglong2 w2[8];
#pragma unroll
        for (int r = 0; r < 8; r++)
            w2[r] = *(const ulonglong2*)&Wt[(r0 + r) * 128 + c];
#pragma unroll
        for (int bb = 0; bb < 8; bb++) {
            ulonglong2 d2 = *(const ulonglong2*)&Dt[bb * 128 + c];
#pragma unroll
            for (int r = 0; r < 8; r++) {
                ffma2(acc[r][bb], w2[r].x, d2.x);
                ffma2(acc[r][bb], w2[r].y, d2.y);
            }
        }
    }

    float accf[8][8];
#pragma unroll
    for (int r = 0; r < 8; r++)
#pragma unroll
        for (int bb = 0; bb < 8; bb++) {
            float2 f = unpack2(acc[r][bb]);
            float v = f.x + f.y;
#pragma unroll
            for (int off = 16; off; off >>= 1)
                v += __shfl_xor_sync(0xffffffffu, v, off);
            accf[r][bb] = v;
        }

    const int bsel = lane & 7;
#pragma unroll
    for (int half = 0; half < 2; half++) {
        const int rr = (lane >> 3) + half * 4;
        float res = 0.0f;
#pragma unroll
        for (int r = 0; r < 8; r++)
#pragma unroll
            for (int bb = 0; bb < 8; bb++)
                if (r == rr && bb == bsel) res = accf[r][bb];
        g_wpart[((size_t)ks * 8 + bsel) * 4096 + o0 + r0 + rr] = res;
    }
}

// ---------------- combine 2 K-partials + bias + final per-row L2 norm ----------------
__global__ __launch_bounds__(256) void k_final(const float* __restrict__ bias,
                                               float* __restrict__ out) {
    const int b = blockIdx.x;
    float v[16];
    float ss = 0.0f;
#pragma unroll
    for (int t = 0; t < 16; t++) {
        const int o = threadIdx.x + t * 256;
        float val = g_wpart[(size_t)b * 4096 + o]
                  + g_wpart[(size_t)(8 + b) * 4096 + o]
                  + bias[o];
        v[t] = val;
        ss += val * val;
    }
#pragma unroll
    for (int off = 16; off; off >>= 1) ss += __shfl_xor_sync(0xffffffffu, ss, off);
    __shared__ float r[8];
    __shared__ float sc;
    const int lane = threadIdx.x & 31, warp = threadIdx.x >> 5;
    if (lane == 0) r[warp] = ss;
    __syncthreads();
    if (threadIdx.x == 0) {
        float tt = 0.0f;
#pragma unroll
        for (int i = 0; i < 8; i++) tt += r[i];
        sc = 1.0f / fmaxf(sqrtf(tt), EPSN);
    }
    __syncthreads();
    float* ob = out + (size_t)b * 4096;
#pragma unroll
    for (int t = 0; t < 16; t++) ob[threadIdx.x + t * 256] = v[t] * sc;
}

// ---------------- launch ----------------
extern "C" void kernel_launch(void* const* d_in, const int* in_sizes, int n_in,
                              void* d_out, int out_size) {
    const float* x        = (const float*)d_in[0];
    const float* conv_w   = (const float*)d_in[1];
    const float* centers  = (const float*)d_in[2];
    const float* whiten_w = (const float*)d_in[3];
    const float* whiten_b = (const float*)d_in[4];
    float* out = (float*)d_out;

    static int attr_set = 0;
    if (!attr_set) {
        cudaFuncSetAttribute(k_whiten, cudaFuncAttributeMaxDynamicSharedMemorySize, 184320);
        cudaFuncSetAttribute(k_fused, cudaFuncAttributeMaxDynamicSharedMemorySize, 87296);
        attr_set = 1;
    }

    k_prep<<<64, 512>>>(conv_w);
    k_fused<<<dim3(25, 8), 256, 87296>>>(x, whiten_w);
    k_post<<<dim3(16, 8), 256>>>(centers);
    k_whiten<<<128, 256, 184320>>>(whiten_w);
    k_final<<<8, 256>>>(whiten_b, out);
}

// round 15
// speedup vs baseline: 1.0804x; 1.0804x over previous
#include <cuda_runtime.h>
#include <math.h>
#include <stdint.h>

// ---------------- scratch (device globals, no allocation) ----------------
typedef unsigned long long ull;
__device__ float g_cwT[512 * 64];          // conv_w transposed [d][k]
__device__ float g_vpart[25 * 8 * 32768];  // [ntile][b][d*64+k] vlad partials
__device__ float g_vlad[8 * 32768];        // [b][d*64+k] centered + scaled desc
__device__ float g_asum[8 * 64];           // [b][k] total assign sums
__device__ float g_ksum[8 * 64];           // [b][k] sum of squares over d
__device__ unsigned g_cntb[8];             // per-batch block-completion counters
__device__ float g_wpart[2 * 8 * 4096];    // [ksplit][b][out] whiten partials

#define EPSN 1e-12f

__device__ __forceinline__ void ffma2(ull& acc, ull a, ull b) {
    asm("fma.rn.f32x2 %0, %1, %2, %0;" : "+l"(acc) : "l"(a), "l"(b));
}
__device__ __forceinline__ ull pack2(float v) {
    ull r; asm("mov.b64 %0, {%1, %1};" : "=l"(r) : "f"(v)); return r;
}
__device__ __forceinline__ float2 unpack2(ull v) {
    float2 f; asm("mov.b64 {%0, %1}, %2;" : "=f"(f.x), "=f"(f.y) : "l"(v)); return f;
}
__device__ __forceinline__ void cpa16(uint32_t s, const void* g) {
    asm volatile("cp.async.cg.shared.global [%0], [%1], 16;" :: "r"(s), "l"(g));
}
__device__ __forceinline__ void cpa_commit() { asm volatile("cp.async.commit_group;"); }
__device__ __forceinline__ void pref_l2(const void* p) {
    asm volatile("prefetch.global.L2 [%0];" :: "l"(p));
}

// ---------------- prep: transpose conv_w + zero accumulators + reset counters ----------------
__global__ void k_prep(const float* __restrict__ cw) {
    const int k = blockIdx.x;
    const int d = threadIdx.x;
    g_cwT[d * 64 + k] = cw[k * 512 + d];
    if (blockIdx.x == 0) {
        g_asum[d & 511] = 0.0f;
        g_ksum[d & 511] = 0.0f;
        if (d < 8) g_cntb[d] = 0u;
    }
}

// ---------------- fused scores + softmax + vlad-gemm (+ L2 warm of W) ----------------
// grid (25, 8): n-tile of 64, batch. block 256 = 16x16. 85KB dyn smem, occ 2.
// (round-13 proven version — 174.4us total)
__global__ __launch_bounds__(256, 2) void k_fused(const float* __restrict__ x,
                                                  const float* __restrict__ W) {
    extern __shared__ __align__(16) float smf[];
    float* XB0 = smf;
    float* XB1 = smf + 4352;
    float* CB0 = smf + 8704;
    float* CB1 = smf + 13056;
    float* SC  = smf + 17408;          // scores [k][n] then assignT [n][k]
    float* inv_sum = smf + 21760;      // 64 floats

    const int b = blockIdx.y;
    const int n0 = blockIdx.x * 64;
    const int t = threadIdx.x;
    const int tx = t & 15;
    const int ty = t >> 4;
    const int cta = blockIdx.y * 25 + blockIdx.x;   // 0..199

    const float* xb = x + (size_t)b * 512 * 1600;

    // W L2-warm: 16 iterations x 256 threads = 4096 lines/CTA (512KB), 200 CTAs = 102MB
    auto warm = [&](int iter) {
        const int L = (cta * 16 + iter) * 256 + t;   // < 819200
        const int row = L / 200;                      // < 4096
        const int rem = L % 200;
        const int half = rem / 100;
        const int li = rem % 100;
        pref_l2(W + (size_t)row * 32768 + half * 16384 + li * 32);
    };

    const uint32_t sx0 = (uint32_t)__cvta_generic_to_shared(XB0);
    const uint32_t sx1 = (uint32_t)__cvta_generic_to_shared(XB1);
    const uint32_t sc0 = (uint32_t)__cvta_generic_to_shared(CB0);
    const uint32_t sc1 = (uint32_t)__cvta_generic_to_shared(CB1);
    const int qdd = t >> 4;
    const int qn4 = t & 15;

    auto stage1 = [&](int tile, int buf) {
        const int d0 = tile * 64;
        const uint32_t bx = buf ? sx1 : sx0;
        const uint32_t bc = buf ? sc1 : sc0;
#pragma unroll
        for (int i = 0; i < 4; i++) {
            const int dd = qdd + i * 16;
            cpa16(bx + (uint32_t)((dd * 68 + qn4 * 4) * 4),
                  xb + (size_t)(d0 + dd) * 1600 + n0 + qn4 * 4);
            cpa16(bc + (uint32_t)((dd * 68 + qn4 * 4) * 4),
                  g_cwT + (d0 + dd) * 64 + qn4 * 4);
        }
        cpa_commit();
    };

    ull acc[4][2];
#pragma unroll
    for (int i = 0; i < 4; i++) { acc[i][0] = 0ULL; acc[i][1] = 0ULL; }

    stage1(0, 0);
    for (int tile = 0; tile < 8; tile++) {
        const int buf = tile & 1;
        if (tile < 7) {
            stage1(tile + 1, buf ^ 1);
            asm volatile("cp.async.wait_group 1;");
        } else {
            asm volatile("cp.async.wait_group 0;");
        }
        __syncthreads();
        warm(tile);

        const float* CS = buf ? CB1 : CB0;
        const float* XS = buf ? XB1 : XB0;
#pragma unroll 8
        for (int dd = 0; dd < 64; dd++) {
            float4 a = *(const float4*)&CS[dd * 68 + ty * 4];
            ulonglong2 f2 = *(const ulonglong2*)&XS[dd * 68 + tx * 4];
            ull a0 = pack2(a.x), a1 = pack2(a.y), a2 = pack2(a.z), a3 = pack2(a.w);
            ffma2(acc[0][0], a0, f2.x); ffma2(acc[0][1], a0, f2.y);
            ffma2(acc[1][0], a1, f2.x); ffma2(acc[1][1], a1, f2.y);
            ffma2(acc[2][0], a2, f2.x); ffma2(acc[2][1], a2, f2.y);
            ffma2(acc[3][0], a3, f2.x); ffma2(acc[3][1], a3, f2.y);
        }
        __syncthreads();
    }

#pragma unroll
    for (int i = 0; i < 4; i++)
#pragma unroll
        for (int p = 0; p < 2; p++) {
            float2 u = unpack2(acc[i][p]);
            SC[(ty * 4 + i) * 68 + tx * 4 + 2 * p]     = u.x;
            SC[(ty * 4 + i) * 68 + tx * 4 + 2 * p + 1] = u.y;
        }
    __syncthreads();

    if (t < 64) {
        const int n = t;
        float mx = -1e30f;
#pragma unroll 8
        for (int k = 0; k < 64; k++) mx = fmaxf(mx, SC[k * 68 + n]);
        float s = 0.0f;
#pragma unroll 8
        for (int k = 0; k < 64; k++) {
            float e = __expf(SC[k * 68 + n] - mx);
            SC[k * 68 + n] = e;
            s += e;
        }
        inv_sum[n] = 1.0f / s;
    }
    __syncthreads();
    if (t < 64) {
        const int k = t;
        float s = 0.0f;
#pragma unroll 8
        for (int nn = 0; nn < 64; nn++) {
            float a = SC[k * 68 + nn] * inv_sum[nn];
            SC[k * 68 + nn] = a;
            s += a;
        }
        atomicAdd(&g_asum[b * 64 + k], s);
    }
    __syncthreads();
    {
        float tmp[16];
#pragma unroll
        for (int i = 0; i < 16; i++) {
            const int idx = t + i * 256;
            tmp[i] = SC[(idx >> 6) * 68 + (idx & 63)];
        }
        __syncthreads();
#pragma unroll
        for (int i = 0; i < 16; i++) {
            const int idx = t + i * 256;
            SC[(idx & 63) * 68 + (idx >> 6)] = tmp[i];
        }
    }

    auto stage2 = [&](int tile, int buf) {
        const int d0 = tile * 64;
        const uint32_t bx = buf ? sx1 : sx0;
#pragma unroll
        for (int i = 0; i < 4; i++) {
            const int dd = qdd + i * 16;
            cpa16(bx + (uint32_t)((dd * 68 + qn4 * 4) * 4),
                  xb + (size_t)(d0 + dd) * 1600 + n0 + qn4 * 4);
        }
        cpa_commit();
    };

    float* vp = g_vpart + ((size_t)blockIdx.x * 8 + b) * 32768;
    __syncthreads();
    stage2(0, 0);
    for (int tile = 0; tile < 8; tile++) {
        const int buf = tile & 1;
        if (tile < 7) {
            stage2(tile + 1, buf ^ 1);
            asm volatile("cp.async.wait_group 1;");
        } else {
            asm volatile("cp.async.wait_group 0;");
        }
        __syncthreads();
        warm(8 + tile);

        const float* XS2 = buf ? XB1 : XB0;
        ull acc2[4][2];
#pragma unroll
        for (int i = 0; i < 4; i++) { acc2[i][0] = 0ULL; acc2[i][1] = 0ULL; }
#pragma unroll 4
        for (int nn = 0; nn < 64; nn++) {
            ulonglong2 a2 = *(const ulonglong2*)&SC[nn * 68 + tx * 4];
            ull f0 = pack2(XS2[(ty * 4 + 0) * 68 + nn]);
            ull f1 = pack2(XS2[(ty * 4 + 1) * 68 + nn]);
            ull f2p = pack2(XS2[(ty * 4 + 2) * 68 + nn]);
            ull f3 = pack2(XS2[(ty * 4 + 3) * 68 + nn]);
            ffma2(acc2[0][0], f0, a2.x);  ffma2(acc2[0][1], f0, a2.y);
            ffma2(acc2[1][0], f1, a2.x);  ffma2(acc2[1][1], f1, a2.y);
            ffma2(acc2[2][0], f2p, a2.x); ffma2(acc2[2][1], f2p, a2.y);
            ffma2(acc2[3][0], f3, a2.x);  ffma2(acc2[3][1], f3, a2.y);
        }
        const int d0 = tile * 64;
#pragma unroll
        for (int i = 0; i < 4; i++) {
            const int d = d0 + ty * 4 + i;
            float2 lo = unpack2(acc2[i][0]);
            float2 hi = unpack2(acc2[i][1]);
            float4 o; o.x = lo.x; o.y = lo.y; o.z = hi.x; o.w = hi.y;
            *(float4*)&vp[d * 64 + tx * 4] = o;
        }
        __syncthreads();
    }
}

// ---------------- post: sum 25 partials + centers fold + norms + scale ----------------
// grid (16, 8) = 128 CTAs, SINGLE WAVE. block 256; two float4 per thread.
__global__ __launch_bounds__(256) void k_post(const float* __restrict__ centers) {
    const int b = blockIdx.y;
    const int t = threadIdx.x;
    const int q = t & 15;

    const float4* c4p = (const float4*)centers;
    const float4* A4p = (const float4*)(g_asum + b * 64);
    const float4 A4 = A4p[q];

    float4 v[2];
    float4 ssq = make_float4(0.f, 0.f, 0.f, 0.f);
#pragma unroll
    for (int h = 0; h < 2; h++) {
        const int i4 = blockIdx.x * 512 + h * 256 + t;
        float4 acc = make_float4(0.f, 0.f, 0.f, 0.f);
#pragma unroll
        for (int s = 0; s < 25; s++) {
            float4 p = *(const float4*)(g_vpart + ((size_t)s * 8 + b) * 32768 + (size_t)i4 * 4);
            acc.x += p.x; acc.y += p.y; acc.z += p.z; acc.w += p.w;
        }
        const float4 c = c4p[i4];
        acc.x -= A4.x * c.x; acc.y -= A4.y * c.y; acc.z -= A4.z * c.z; acc.w -= A4.w * c.w;
        v[h] = acc;
        ssq.x += acc.x * acc.x; ssq.y += acc.y * acc.y;
        ssq.z += acc.z * acc.z; ssq.w += acc.w * acc.w;
    }

    __shared__ __align__(16) float4 red[256];
    red[t] = ssq;
    __syncthreads();
    if (t < 16) {
        float4 s = make_float4(0.f, 0.f, 0.f, 0.f);
#pragma unroll
        for (int j = 0; j < 16; j++) {
            float4 r = red[t + j * 16];
            s.x += r.x; s.y += r.y; s.z += r.z; s.w += r.w;
        }
        atomicAdd(&g_ksum[b * 64 + t * 4 + 0], s.x);
        atomicAdd(&g_ksum[b * 64 + t * 4 + 1], s.y);
        atomicAdd(&g_ksum[b * 64 + t * 4 + 2], s.z);
        atomicAdd(&g_ksum[b * 64 + t * 4 + 3], s.w);
    }
    __threadfence();
    __syncthreads();

    if (t == 0) {
        atomicAdd(&g_cntb[b], 1u);
        while (*(volatile unsigned*)&g_cntb[b] < 16u) { }
    }
    __syncthreads();
    __threadfence();

    __shared__ float sc_s[64];
    __shared__ float wred[2];
    float inv = 0.0f, contrib = 0.0f;
    if (t < 64) {
        float kv = *(volatile float*)&g_ksum[b * 64 + t];
        inv = 1.0f / fmaxf(sqrtf(kv), EPSN);
        contrib = kv * inv * inv;
    }
    float csum = contrib;
#pragma unroll
    for (int off = 16; off; off >>= 1) csum += __shfl_xor_sync(0xffffffffu, csum, off);
    if (t < 64 && (t & 31) == 0) wred[t >> 5] = csum;
    __syncthreads();
    if (t < 64) {
        float g = wred[0] + wred[1];
        sc_s[t] = inv * (1.0f / fmaxf(sqrtf(g), EPSN));
    }
    __syncthreads();

    const float4 sc4 = *(const float4*)&sc_s[q * 4];
    float4* vp = (float4*)(g_vlad + (size_t)b * 32768);
#pragma unroll
    for (int h = 0; h < 2; h++) {
        const int i4 = blockIdx.x * 512 + h * 256 + t;
        float4 o = v[h];
        o.x *= sc4.x; o.y *= sc4.y; o.z *= sc4.z; o.w *= sc4.w;
        vp[i4] = o;
    }
}

// ---------------- whitening GEMM v5: 64 rows/CTA, K-split 2, 5-stage ring ----------------
// grid 128 = 64 rowtiles x 2 K-halves = single wave, 1 CTA/SM. block 256 (8 warps x 8 rows).
// smem: W [5][8192]f at 0, D [5][1024]f at 40960 -> 180KB dyn.
__global__ __launch_bounds__(256, 1) void k_whiten(const float* __restrict__ W) {
    extern __shared__ __align__(16) float smw[];

    const int rowtile = blockIdx.x >> 1;
    const int ks = blockIdx.x & 1;
    const int o0 = rowtile * 64;
    const int jbase = ks * 16384;

    const int t = threadIdx.x;
    const int lane = t & 31;
    const int warp = t >> 5;
    const int r0 = warp * 8;
    const int c = lane * 4;
    const int wr = t >> 5;
    const int wc4 = t & 31;

    ull acc[8][8];
#pragma unroll
    for (int r = 0; r < 8; r++)
#pragma unroll
        for (int bb = 0; bb < 8; bb++) acc[r][bb] = 0ULL;

    const uint32_t sbase = (uint32_t)__cvta_generic_to_shared(smw);
    const float* Wbase = W + (size_t)o0 * 32768 + jbase;
    const float* Dbase = g_vlad + jbase;

    auto stage = [&](int tile, int buf) {
        const int jc = tile * 128 + wc4 * 4;
#pragma unroll
        for (int i = 0; i < 8; i++) {
            const int r = wr * 8 + i;
            cpa16(sbase + (uint32_t)((buf * 8192 + r * 128 + wc4 * 4) * 4),
                  Wbase + (size_t)r * 32768 + jc);
        }
        cpa16(sbase + (uint32_t)((40960 + buf * 1024 + wr * 128 + wc4 * 4) * 4),
              Dbase + (size_t)wr * 32768 + jc);
        cpa_commit();
    };

    stage(0, 0); stage(1, 1); stage(2, 2); stage(3, 3);

    int buf = 0, nbuf = 4;
    for (int tile = 0; tile < 128; tile++) {
        const int rem = 127 - tile;
        if (rem >= 3)      asm volatile("cp.async.wait_group 3;");
        else if (rem == 2) asm volatile("cp.async.wait_group 2;");
        else if (rem == 1) asm volatile("cp.async.wait_group 1;");
        else               asm volatile("cp.async.wait_group 0;");
        __syncthreads();
        if (tile + 4 < 128) {
            stage(tile + 4, nbuf);
            if (++nbuf == 5) nbuf = 0;
        }

        const float* Wt = smw + buf * 8192;
        const float* Dt = smw + 40960 + buf * 1024;
        if (++buf == 5) buf = 0;

        ulonglong2 w2[8];
#pragma unroll
        for (int r = 0; r < 8; r++)
            w2[r] = *(const ulonglong2*)&Wt[(r0 + r) * 128 + c];
#pragma unroll
        for (int bb = 0; bb < 8; bb++) {
            ulonglong2 d2 = *(const ulonglong2*)&Dt[bb * 128 + c];
#pragma unroll
            for (int r = 0; r < 8; r++) {
                ffma2(acc[r][bb], w2[r].x, d2.x);
                ffma2(acc[r][bb], w2[r].y, d2.y);
            }
        }
    }

    float accf[8][8];
#pragma unroll
    for (int r = 0; r < 8; r++)
#pragma unroll
        for (int bb = 0; bb < 8; bb++) {
            float2 f = unpack2(acc[r][bb]);
            float v = f.x + f.y;
#pragma unroll
            for (int off = 16; off; off >>= 1)
                v += __shfl_xor_sync(0xffffffffu, v, off);
            accf[r][bb] = v;
        }

    const int bsel = lane & 7;
#pragma unroll
    for (int half = 0; half < 2; half++) {
        const int rr = (lane >> 3) + half * 4;
        float res = 0.0f;
#pragma unroll
        for (int r = 0; r < 8; r++)
#pragma unroll
            for (int bb = 0; bb < 8; bb++)
                if (r == rr && bb == bsel) res = accf[r][bb];
        g_wpart[((size_t)ks * 8 + bsel) * 4096 + o0 + r0 + rr] = res;
    }
}

// ---------------- combine 2 K-partials + bias + final per-row L2 norm ----------------
__global__ __launch_bounds__(256) void k_final(const float* __restrict__ bias,
                                               float* __restrict__ out) {
    const int b = blockIdx.x;
    float v[16];
    float ss = 0.0f;
#pragma unroll
    for (int t = 0; t < 16; t++) {
        const int o = threadIdx.x + t * 256;
        float val = g_wpart[(size_t)b * 4096 + o]
                  + g_wpart[(size_t)(8 + b) * 4096 + o]
                  + bias[o];
        v[t] = val;
        ss += val * val;
    }
#pragma unroll
    for (int off = 16; off; off >>= 1) ss += __shfl_xor_sync(0xffffffffu, ss, off);
    __shared__ float r[8];
    __shared__ float sc;
    const int lane = threadIdx.x & 31, warp = threadIdx.x >> 5;
    if (lane == 0) r[warp] = ss;
    __syncthreads();
    if (threadIdx.x == 0) {
        float tt = 0.0f;
#pragma unroll
        for (int i = 0; i < 8; i++) tt += r[i];
        sc = 1.0f / fmaxf(sqrtf(tt), EPSN);
    }
    __syncthreads();
    float* ob = out + (size_t)b * 4096;
#pragma unroll
    for (int t = 0; t < 16; t++) ob[threadIdx.x + t * 256] = v[t] * sc;
}

// ---------------- launch ----------------
extern "C" void kernel_launch(void* const* d_in, const int* in_sizes, int n_in,
                              void* d_out, int out_size) {
    const float* x        = (const float*)d_in[0];
    const float* conv_w   = (const float*)d_in[1];
    const float* centers  = (const float*)d_in[2];
    const float* whiten_w = (const float*)d_in[3];
    const float* whiten_b = (const float*)d_in[4];
    float* out = (float*)d_out;

    static int attr_set = 0;
    if (!attr_set) {
        cudaFuncSetAttribute(k_whiten, cudaFuncAttributeMaxDynamicSharedMemorySize, 184320);
        cudaFuncSetAttribute(k_fused, cudaFuncAttributeMaxDynamicSharedMemorySize, 87296);
        attr_set = 1;
    }

    k_prep<<<64, 512>>>(conv_w);
    k_fused<<<dim3(25, 8), 256, 87296>>>(x, whiten_w);
    k_post<<<dim3(16, 8), 256>>>(centers);
    k_whiten<<<128, 256, 184320>>>(whiten_w);
    k_final<<<8, 256>>>(whiten_b, out);
}

// round 16
// speedup vs baseline: 1.1147x; 1.0317x over previous
#include <cuda_runtime.h>
#include <math.h>
#include <stdint.h>

// ---------------- scratch (device globals, no allocation) ----------------
typedef unsigned long long ull;
__device__ float g_cwT[512 * 64];          // conv_w transposed [d][k]
__device__ float g_vpart[25 * 8 * 32768];  // [ntile][b][d*64+k] vlad partials
__device__ float g_vlad[8 * 32768];        // [b][d*64+k] centered + scaled desc
__device__ float g_asum[8 * 64];           // [b][k] total assign sums
__device__ float g_ksum[8 * 64];           // [b][k] sum of squares over d
__device__ unsigned g_cntb[8];             // per-batch completion counters (post phase)
__device__ unsigned g_cntall;              // global completion counter (post -> whiten)
__device__ float g_wpart[2 * 8 * 4096];    // [ksplit][b][out] whiten partials

#define EPSN 1e-12f

__device__ __forceinline__ void ffma2(ull& acc, ull a, ull b) {
    asm("fma.rn.f32x2 %0, %1, %2, %0;" : "+l"(acc) : "l"(a), "l"(b));
}
__device__ __forceinline__ ull pack2(float v) {
    ull r; asm("mov.b64 %0, {%1, %1};" : "=l"(r) : "f"(v)); return r;
}
__device__ __forceinline__ float2 unpack2(ull v) {
    float2 f; asm("mov.b64 {%0, %1}, %2;" : "=f"(f.x), "=f"(f.y) : "l"(v)); return f;
}
__device__ __forceinline__ void cpa16(uint32_t s, const void* g) {
    asm volatile("cp.async.cg.shared.global [%0], [%1], 16;" :: "r"(s), "l"(g));
}
__device__ __forceinline__ void cpa_commit() { asm volatile("cp.async.commit_group;"); }
__device__ __forceinline__ void pref_l2(const void* p) {
    asm volatile("prefetch.global.L2 [%0];" :: "l"(p));
}

// ---------------- prep: transpose conv_w + zero accumulators + reset counters ----------------
__global__ void k_prep(const float* __restrict__ cw) {
    const int k = blockIdx.x;
    const int d = threadIdx.x;
    g_cwT[d * 64 + k] = cw[k * 512 + d];
    if (blockIdx.x == 0) {
        g_asum[d & 511] = 0.0f;
        g_ksum[d & 511] = 0.0f;
        if (d < 8) g_cntb[d] = 0u;
        if (d == 8) g_cntall = 0u;
    }
}

// ---------------- fused scores + softmax + vlad-gemm (+ L2 warm of W) ----------------
// grid (25, 8): n-tile of 64, batch. block 256 = 16x16. 85KB dyn smem, occ 2.
// (round-13 proven version)
__global__ __launch_bounds__(256, 2) void k_fused(const float* __restrict__ x,
                                                  const float* __restrict__ W) {
    extern __shared__ __align__(16) float smf[];
    float* XB0 = smf;
    float* XB1 = smf + 4352;
    float* CB0 = smf + 8704;
    float* CB1 = smf + 13056;
    float* SC  = smf + 17408;          // scores [k][n] then assignT [n][k]
    float* inv_sum = smf + 21760;      // 64 floats

    const int b = blockIdx.y;
    const int n0 = blockIdx.x * 64;
    const int t = threadIdx.x;
    const int tx = t & 15;
    const int ty = t >> 4;
    const int cta = blockIdx.y * 25 + blockIdx.x;   // 0..199

    const float* xb = x + (size_t)b * 512 * 1600;

    auto warm = [&](int iter) {
        const int L = (cta * 16 + iter) * 256 + t;   // < 819200
        const int row = L / 200;                      // < 4096
        const int rem = L % 200;
        const int half = rem / 100;
        const int li = rem % 100;
        pref_l2(W + (size_t)row * 32768 + half * 16384 + li * 32);
    };

    const uint32_t sx0 = (uint32_t)__cvta_generic_to_shared(XB0);
    const uint32_t sx1 = (uint32_t)__cvta_generic_to_shared(XB1);
    const uint32_t sc0 = (uint32_t)__cvta_generic_to_shared(CB0);
    const uint32_t sc1 = (uint32_t)__cvta_generic_to_shared(CB1);
    const int qdd = t >> 4;
    const int qn4 = t & 15;

    auto stage1 = [&](int tile, int buf) {
        const int d0 = tile * 64;
        const uint32_t bx = buf ? sx1 : sx0;
        const uint32_t bc = buf ? sc1 : sc0;
#pragma unroll
        for (int i = 0; i < 4; i++) {
            const int dd = qdd + i * 16;
            cpa16(bx + (uint32_t)((dd * 68 + qn4 * 4) * 4),
                  xb + (size_t)(d0 + dd) * 1600 + n0 + qn4 * 4);
            cpa16(bc + (uint32_t)((dd * 68 + qn4 * 4) * 4),
                  g_cwT + (d0 + dd) * 64 + qn4 * 4);
        }
        cpa_commit();
    };

    ull acc[4][2];
#pragma unroll
    for (int i = 0; i < 4; i++) { acc[i][0] = 0ULL; acc[i][1] = 0ULL; }

    stage1(0, 0);
    for (int tile = 0; tile < 8; tile++) {
        const int buf = tile & 1;
        if (tile < 7) {
            stage1(tile + 1, buf ^ 1);
            asm volatile("cp.async.wait_group 1;");
        } else {
            asm volatile("cp.async.wait_group 0;");
        }
        __syncthreads();
        warm(tile);

        const float* CS = buf ? CB1 : CB0;
        const float* XS = buf ? XB1 : XB0;
#pragma unroll 8
        for (int dd = 0; dd < 64; dd++) {
            float4 a = *(const float4*)&CS[dd * 68 + ty * 4];
            ulonglong2 f2 = *(const ulonglong2*)&XS[dd * 68 + tx * 4];
            ull a0 = pack2(a.x), a1 = pack2(a.y), a2 = pack2(a.z), a3 = pack2(a.w);
            ffma2(acc[0][0], a0, f2.x); ffma2(acc[0][1], a0, f2.y);
            ffma2(acc[1][0], a1, f2.x); ffma2(acc[1][1], a1, f2.y);
            ffma2(acc[2][0], a2, f2.x); ffma2(acc[2][1], a2, f2.y);
            ffma2(acc[3][0], a3, f2.x); ffma2(acc[3][1], a3, f2.y);
        }
        __syncthreads();
    }

#pragma unroll
    for (int i = 0; i < 4; i++)
#pragma unroll
        for (int p = 0; p < 2; p++) {
            float2 u = unpack2(acc[i][p]);
            SC[(ty * 4 + i) * 68 + tx * 4 + 2 * p]     = u.x;
            SC[(ty * 4 + i) * 68 + tx * 4 + 2 * p + 1] = u.y;
        }
    __syncthreads();

    if (t < 64) {
        const int n = t;
        float mx = -1e30f;
#pragma unroll 8
        for (int k = 0; k < 64; k++) mx = fmaxf(mx, SC[k * 68 + n]);
        float s = 0.0f;
#pragma unroll 8
        for (int k = 0; k < 64; k++) {
            float e = __expf(SC[k * 68 + n] - mx);
            SC[k * 68 + n] = e;
            s += e;
        }
        inv_sum[n] = 1.0f / s;
    }
    __syncthreads();
    if (t < 64) {
        const int k = t;
        float s = 0.0f;
#pragma unroll 8
        for (int nn = 0; nn < 64; nn++) {
            float a = SC[k * 68 + nn] * inv_sum[nn];
            SC[k * 68 + nn] = a;
            s += a;
        }
        atomicAdd(&g_asum[b * 64 + k], s);
    }
    __syncthreads();
    {
        float tmp[16];
#pragma unroll
        for (int i = 0; i < 16; i++) {
            const int idx = t + i * 256;
            tmp[i] = SC[(idx >> 6) * 68 + (idx & 63)];
        }
        __syncthreads();
#pragma unroll
        for (int i = 0; i < 16; i++) {
            const int idx = t + i * 256;
            SC[(idx & 63) * 68 + (idx >> 6)] = tmp[i];
        }
    }

    auto stage2 = [&](int tile, int buf) {
        const int d0 = tile * 64;
        const uint32_t bx = buf ? sx1 : sx0;
#pragma unroll
        for (int i = 0; i < 4; i++) {
            const int dd = qdd + i * 16;
            cpa16(bx + (uint32_t)((dd * 68 + qn4 * 4) * 4),
                  xb + (size_t)(d0 + dd) * 1600 + n0 + qn4 * 4);
        }
        cpa_commit();
    };

    float* vp = g_vpart + ((size_t)blockIdx.x * 8 + b) * 32768;
    __syncthreads();
    stage2(0, 0);
    for (int tile = 0; tile < 8; tile++) {
        const int buf = tile & 1;
        if (tile < 7) {
            stage2(tile + 1, buf ^ 1);
            asm volatile("cp.async.wait_group 1;");
        } else {
            asm volatile("cp.async.wait_group 0;");
        }
        __syncthreads();
        warm(8 + tile);

        const float* XS2 = buf ? XB1 : XB0;
        ull acc2[4][2];
#pragma unroll
        for (int i = 0; i < 4; i++) { acc2[i][0] = 0ULL; acc2[i][1] = 0ULL; }
#pragma unroll 4
        for (int nn = 0; nn < 64; nn++) {
            ulonglong2 a2 = *(const ulonglong2*)&SC[nn * 68 + tx * 4];
            ull f0 = pack2(XS2[(ty * 4 + 0) * 68 + nn]);
            ull f1 = pack2(XS2[(ty * 4 + 1) * 68 + nn]);
            ull f2p = pack2(XS2[(ty * 4 + 2) * 68 + nn]);
            ull f3 = pack2(XS2[(ty * 4 + 3) * 68 + nn]);
            ffma2(acc2[0][0], f0, a2.x);  ffma2(acc2[0][1], f0, a2.y);
            ffma2(acc2[1][0], f1, a2.x);  ffma2(acc2[1][1], f1, a2.y);
            ffma2(acc2[2][0], f2p, a2.x); ffma2(acc2[2][1], f2p, a2.y);
            ffma2(acc2[3][0], f3, a2.x);  ffma2(acc2[3][1], f3, a2.y);
        }
        const int d0 = tile * 64;
#pragma unroll
        for (int i = 0; i < 4; i++) {
            const int d = d0 + ty * 4 + i;
            float2 lo = unpack2(acc2[i][0]);
            float2 hi = unpack2(acc2[i][1]);
            float4 o; o.x = lo.x; o.y = lo.y; o.z = hi.x; o.w = hi.y;
            *(float4*)&vp[d * 64 + tx * 4] = o;
        }
        __syncthreads();
    }
}

// ---------------- whitening GEMM v6: fused post-prologue + 64-row GEMM ----------------
// grid 128 = single wave, 1 CTA/SM (all CTAs co-resident -> device barriers safe).
// Prologue: blockIdx.x = px*8+pb slice of the post work (sum partials, centers,
//   norms, scale, write g_vlad), per-batch release (16) then global release (128).
// Mainloop: round-13 proven 64 rows/CTA, K-split 2, 5-stage cp.async ring.
__global__ __launch_bounds__(256, 1) void k_whiten(const float* __restrict__ W,
                                                   const float* __restrict__ centers) {
    extern __shared__ __align__(16) float smw[];

    const int t = threadIdx.x;

    // ======== post prologue ========
    {
        const int pb = blockIdx.x & 7;     // batch
        const int px = blockIdx.x >> 3;    // d-tile 0..15
        const int q = t & 15;

        const float4* c4p = (const float4*)centers;
        const float4 A4 = ((const float4*)(g_asum + pb * 64))[q];

        float4 v[2];
        float4 ssq = make_float4(0.f, 0.f, 0.f, 0.f);
#pragma unroll
        for (int h = 0; h < 2; h++) {
            const int i4 = px * 512 + h * 256 + t;
            float4 acc = make_float4(0.f, 0.f, 0.f, 0.f);
#pragma unroll
            for (int s = 0; s < 25; s++) {
                float4 p = *(const float4*)(g_vpart + ((size_t)s * 8 + pb) * 32768 + (size_t)i4 * 4);
                acc.x += p.x; acc.y += p.y; acc.z += p.z; acc.w += p.w;
            }
            const float4 c = c4p[i4];
            acc.x -= A4.x * c.x; acc.y -= A4.y * c.y; acc.z -= A4.z * c.z; acc.w -= A4.w * c.w;
            v[h] = acc;
            ssq.x += acc.x * acc.x; ssq.y += acc.y * acc.y;
            ssq.z += acc.z * acc.z; ssq.w += acc.w * acc.w;
        }

        // per-k sumsq reduce via smem (reuse dyn smem before GEMM staging)
        float4* red = (float4*)smw;
        red[t] = ssq;
        __syncthreads();
        if (t < 16) {
            float4 s = make_float4(0.f, 0.f, 0.f, 0.f);
#pragma unroll
            for (int j = 0; j < 16; j++) {
                float4 r = red[t + j * 16];
                s.x += r.x; s.y += r.y; s.z += r.z; s.w += r.w;
            }
            atomicAdd(&g_ksum[pb * 64 + t * 4 + 0], s.x);
            atomicAdd(&g_ksum[pb * 64 + t * 4 + 1], s.y);
            atomicAdd(&g_ksum[pb * 64 + t * 4 + 2], s.z);
            atomicAdd(&g_ksum[pb * 64 + t * 4 + 3], s.w);
        }
        __threadfence();
        __syncthreads();

        // per-batch release: all 16 slices of this batch done
        if (t == 0) {
            atomicAdd(&g_cntb[pb], 1u);
            while (*(volatile unsigned*)&g_cntb[pb] < 16u) { }
        }
        __syncthreads();
        __threadfence();

        // combined scale
        float* sc_s = smw;          // 64 floats
        float* wred = smw + 64;     // 2 floats
        float inv = 0.0f, contrib = 0.0f;
        if (t < 64) {
            float kv = *(volatile float*)&g_ksum[pb * 64 + t];
            inv = 1.0f / fmaxf(sqrtf(kv), EPSN);
            contrib = kv * inv * inv;
        }
        float csum = contrib;
#pragma unroll
        for (int off = 16; off; off >>= 1) csum += __shfl_xor_sync(0xffffffffu, csum, off);
        if (t < 64 && (t & 31) == 0) wred[t >> 5] = csum;
        __syncthreads();
        if (t < 64) {
            float g = wred[0] + wred[1];
            sc_s[t] = inv * (1.0f / fmaxf(sqrtf(g), EPSN));
        }
        __syncthreads();

        const float4 sc4 = *(const float4*)&sc_s[q * 4];
        float4* vpo = (float4*)(g_vlad + (size_t)pb * 32768);
#pragma unroll
        for (int h = 0; h < 2; h++) {
            const int i4 = px * 512 + h * 256 + t;
            float4 o = v[h];
            o.x *= sc4.x; o.y *= sc4.y; o.z *= sc4.z; o.w *= sc4.w;
            vpo[i4] = o;
        }
        __threadfence();
        __syncthreads();

        // global release: all 128 slices done -> g_vlad complete
        if (t == 0) {
            atomicAdd(&g_cntall, 1u);
            while (*(volatile unsigned*)&g_cntall < 128u) { }
        }
        __syncthreads();
        __threadfence();
    }

    // ======== whiten mainloop (round-13 proven) ========
    const int rowtile = blockIdx.x >> 1;
    const int ks = blockIdx.x & 1;
    const int o0 = rowtile * 64;
    const int jbase = ks * 16384;

    const int lane = t & 31;
    const int warp = t >> 5;
    const int r0 = warp * 8;
    const int c = lane * 4;
    const int wr = t >> 5;
    const int wc4 = t & 31;

    ull acc[8][8];
#pragma unroll
    for (int r = 0; r < 8; r++)
#pragma unroll
        for (int bb = 0; bb < 8; bb++) acc[r][bb] = 0ULL;

    const uint32_t sbase = (uint32_t)__cvta_generic_to_shared(smw);
    const float* Wbase = W + (size_t)o0 * 32768 + jbase;
    const float* Dbase = g_vlad + jbase;

    auto stage = [&](int tile, int buf) {
        const int jc = tile * 128 + wc4 * 4;
#pragma unroll
        for (int i = 0; i < 8; i++) {
            const int r = wr * 8 + i;
            cpa16(sbase + (uint32_t)((buf * 8192 + r * 128 + wc4 * 4) * 4),
                  Wbase + (size_t)r * 32768 + jc);
        }
        cpa16(sbase + (uint32_t)((40960 + buf * 1024 + wr * 128 + wc4 * 4) * 4),
              Dbase + (size_t)wr * 32768 + jc);
        cpa_commit();
    };

    stage(0, 0); stage(1, 1); stage(2, 2); stage(3, 3);

    int buf = 0, nbuf = 4;
    for (int tile = 0; tile < 128; tile++) {
        const int rem = 127 - tile;
        if (rem >= 3)      asm volatile("cp.async.wait_group 3;");
        else if (rem == 2) asm volatile("cp.async.wait_group 2;");
        else if (rem == 1) asm volatile("cp.async.wait_group 1;");
        else               asm volatile("cp.async.wait_group 0;");
        __syncthreads();
        if (tile + 4 < 128) {
            stage(tile + 4, nbuf);
            if (++nbuf == 5) nbuf = 0;
        }

        const float* Wt = smw + buf * 8192;
        const float* Dt = smw + 40960 + buf * 1024;
        if (++buf == 5) buf = 0;

        ulonglong2 w2[8];
#pragma unroll
        for (int r = 0; r < 8; r++)
            w2[r] = *(const ulonglong2*)&Wt[(r0 + r) * 128 + c];
#pragma unroll
        for (int bb = 0; bb < 8; bb++) {
            ulonglong2 d2 = *(const ulonglong2*)&Dt[bb * 128 + c];
#pragma unroll
            for (int r = 0; r < 8; r++) {
                ffma2(acc[r][bb], w2[r].x, d2.x);
                ffma2(acc[r][bb], w2[r].y, d2.y);
            }
        }
    }

    float accf[8][8];
#pragma unroll
    for (int r = 0; r < 8; r++)
#pragma unroll
        for (int bb = 0; bb < 8; bb++) {
            float2 f = unpack2(acc[r][bb]);
            float v = f.x + f.y;
#pragma unroll
            for (int off = 16; off; off >>= 1)
                v += __shfl_xor_sync(0xffffffffu, v, off);
            accf[r][bb] = v;
        }

    const int bsel = lane & 7;
#pragma unroll
    for (int half = 0; half < 2; half++) {
        const int rr = (lane >> 3) + half * 4;
        float res = 0.0f;
#pragma unroll
        for (int r = 0; r < 8; r++)
#pragma unroll
            for (int bb = 0; bb < 8; bb++)
                if (r == rr && bb == bsel) res = accf[r][bb];
        g_wpart[((size_t)ks * 8 + bsel) * 4096 + o0 + r0 + rr] = res;
    }
}

// ---------------- combine 2 K-partials + bias + final per-row L2 norm ----------------
__global__ __launch_bounds__(256) void k_final(const float* __restrict__ bias,
                                               float* __restrict__ out) {
    const int b = blockIdx.x;
    float v[16];
    float ss = 0.0f;
#pragma unroll
    for (int t = 0; t < 16; t++) {
        const int o = threadIdx.x + t * 256;
        float val = g_wpart[(size_t)b * 4096 + o]
                  + g_wpart[(size_t)(8 + b) * 4096 + o]
                  + bias[o];
        v[t] = val;
        ss += val * val;
    }
#pragma unroll
    for (int off = 16; off; off >>= 1) ss += __shfl_xor_sync(0xffffffffu, ss, off);
    __shared__ float r[8];
    __shared__ float sc;
    const int lane = threadIdx.x & 31, warp = threadIdx.x >> 5;
    if (lane == 0) r[warp] = ss;
    __syncthreads();
    if (threadIdx.x == 0) {
        float tt = 0.0f;
#pragma unroll
        for (int i = 0; i < 8; i++) tt += r[i];
        sc = 1.0f / fmaxf(sqrtf(tt), EPSN);
    }
    __syncthreads();
    float* ob = out + (size_t)b * 4096;
#pragma unroll
    for (int t = 0; t < 16; t++) ob[threadIdx.x + t * 256] = v[t] * sc;
}

// ---------------- launch ----------------
extern "C" void kernel_launch(void* const* d_in, const int* in_sizes, int n_in,
                              void* d_out, int out_size) {
    const float* x        = (const float*)d_in[0];
    const float* conv_w   = (const float*)d_in[1];
    const float* centers  = (const float*)d_in[2];
    const float* whiten_w = (const float*)d_in[3];
    const float* whiten_b = (const float*)d_in[4];
    float* out = (float*)d_out;

    static int attr_set = 0;
    if (!attr_set) {
        cudaFuncSetAttribute(k_whiten, cudaFuncAttributeMaxDynamicSharedMemorySize, 184320);
        cudaFuncSetAttribute(k_fused, cudaFuncAttributeMaxDynamicSharedMemorySize, 87296);
        attr_set = 1;
    }

    k_prep<<<64, 512>>>(conv_w);
    k_fused<<<dim3(25, 8), 256, 87296>>>(x, whiten_w);
    k_whiten<<<128, 256, 184320>>>(whiten_w, centers);
    k_final<<<8, 256>>>(whiten_b, out);
}